// round 1
// baseline (speedup 1.0000x reference)
#include <cuda_runtime.h>
#include <math.h>

// ---------------- problem constants ----------------
#define M_TOT 131072          // B*nW*T*N == B*T*H*W tokens
#define CDIM  128
#define HIDDEN 512
#define HEADS 4
#define HD 32

// ---------------- scratch (device globals, no runtime alloc) ----------------
__device__ float g_xw  [(size_t)M_TOT * CDIM];        // gathered windows / reused as proj out
__device__ float g_qkv [(size_t)M_TOT * 3 * CDIM];    // qkv / reused: xln overlay
__device__ float g_attn[(size_t)M_TOT * CDIM];        // attention out / reused: pre-LN1
__device__ float g_xres[(size_t)M_TOT * CDIM];        // shortcut + attn (residual stream)
__device__ float g_h1  [(size_t)M_TOT * HIDDEN];      // MLP hidden

// ---------------- gather: roll(-4,-4) + window partition ----------------
// xw[(b*256+w)*128 + t*64 + n][c] = x[(b*2+t), (wh*8+i+4)%128, (ww*8+j+4)%128, c]
__global__ void gather_kernel(const float* __restrict__ xv, float* __restrict__ xw) {
    int idx = blockIdx.x * blockDim.x + threadIdx.x;   // float4 index, M_TOT*32 total
    int c4  = idx & 31;
    int row = idx >> 5;
    int b_  = row >> 7;          // window index 0..1023
    int tt  = row & 127;         // token within window-pair
    int b = b_ >> 8, w = b_ & 255;
    int wh = w >> 4, ww = w & 15;
    int t = tt >> 6, n = tt & 63;
    int i = n >> 3, j = n & 7;
    int oh = (wh * 8 + i + 4) & 127;
    int ow = (ww * 8 + j + 4) & 127;
    size_t src4 = ((size_t)((b * 2 + t) * 16384 + oh * 128 + ow)) * 32 + c4;
    reinterpret_cast<float4*>(xw)[idx] = reinterpret_cast<const float4*>(xv)[src4];
}

// ---------------- scatter: window reverse + roll(+4,+4) + residual ----------------
__global__ void scatter_kernel(const float* __restrict__ xv, const float* __restrict__ proj,
                               float* __restrict__ xres) {
    int idx = blockIdx.x * blockDim.x + threadIdx.x;
    int c4  = idx & 31;
    int row = idx >> 5;
    int b_  = row >> 7;
    int tt  = row & 127;
    int b = b_ >> 8, w = b_ & 255;
    int wh = w >> 4, ww = w & 15;
    int t = tt >> 6, n = tt & 63;
    int i = n >> 3, j = n & 7;
    int oh = (wh * 8 + i + 4) & 127;
    int ow = (ww * 8 + j + 4) & 127;
    size_t dst4 = ((size_t)((b * 2 + t) * 16384 + oh * 128 + ow)) * 32 + c4;
    float4 a = reinterpret_cast<const float4*>(xv)[dst4];
    float4 p = reinterpret_cast<const float4*>(proj)[idx];
    a.x += p.x; a.y += p.y; a.z += p.z; a.w += p.w;
    reinterpret_cast<float4*>(xres)[dst4] = a;
}

// ---------------- generic fp32 GEMM: out[M,N] = A[M,K] @ W[N,K]^T + bias (+epi) ----------------
// EPI: 0 = bias, 1 = bias + exact gelu, 2 = bias + residual add
template <int EPI>
__global__ void gemm_kernel(const float* __restrict__ A, const float* __restrict__ Wt,
                            const float* __restrict__ bias, const float* __restrict__ res,
                            float* __restrict__ out, int Nn, int K) {
    __shared__ float As[64][17];
    __shared__ float Bs[64][17];
    int tid = threadIdx.x;                 // 256 threads
    int tx = tid & 15, ty = tid >> 4;
    int bm = blockIdx.y * 64, bn = blockIdx.x * 64;
    int lr = tid >> 2;                     // 0..63
    int lc = (tid & 3) * 4;                // 0,4,8,12
    float acc[4][4];
#pragma unroll
    for (int i = 0; i < 4; i++)
#pragma unroll
        for (int j = 0; j < 4; j++) acc[i][j] = 0.f;

    for (int k0 = 0; k0 < K; k0 += 16) {
        float4 av = *reinterpret_cast<const float4*>(A  + (size_t)(bm + lr) * K + k0 + lc);
        float4 bv = *reinterpret_cast<const float4*>(Wt + (size_t)(bn + lr) * K + k0 + lc);
        As[lr][lc + 0] = av.x; As[lr][lc + 1] = av.y; As[lr][lc + 2] = av.z; As[lr][lc + 3] = av.w;
        Bs[lr][lc + 0] = bv.x; Bs[lr][lc + 1] = bv.y; Bs[lr][lc + 2] = bv.z; Bs[lr][lc + 3] = bv.w;
        __syncthreads();
#pragma unroll
        for (int k = 0; k < 16; k++) {
            float a[4], bq[4];
#pragma unroll
            for (int i = 0; i < 4; i++) a[i]  = As[ty * 4 + i][k];
#pragma unroll
            for (int j = 0; j < 4; j++) bq[j] = Bs[tx * 4 + j][k];
#pragma unroll
            for (int i = 0; i < 4; i++)
#pragma unroll
                for (int j = 0; j < 4; j++) acc[i][j] += a[i] * bq[j];
        }
        __syncthreads();
    }
#pragma unroll
    for (int i = 0; i < 4; i++) {
        int r = bm + ty * 4 + i;
#pragma unroll
        for (int j = 0; j < 4; j++) {
            int c = bn + tx * 4 + j;
            float v = acc[i][j] + bias[c];
            if (EPI == 1) v = 0.5f * v * (1.0f + erff(v * 0.7071067811865475f));
            if (EPI == 2) v += res[(size_t)r * Nn + c];
            out[(size_t)r * Nn + c] = v;
        }
    }
}

// ---------------- fused window attention: one block per (window, head) ----------------
__global__ void attn_kernel(const float* __restrict__ qkv, const float* __restrict__ rpb,
                            float* __restrict__ attout) {
    int win  = blockIdx.x;     // 0..1023
    int head = blockIdx.y;     // 0..3
    __shared__ float Ks[128 * 32];
    __shared__ float Vs[128 * 32];
    __shared__ float Ps[64 * 64];   // rpb + shift-mask, [kn][qn]
    int tid = threadIdx.x;          // 128

    for (int e = tid; e < 128 * 32; e += 128) {
        int kt = e >> 5, d = e & 31;
        size_t base = ((size_t)(win * 128 + kt)) * 384 + head * 32 + d;
        Ks[e] = qkv[base + 128];
        Vs[e] = qkv[base + 256];
    }
    int w = win & 255;
    int wh = w >> 4, ww = w & 15;
    for (int e = tid; e < 64 * 64; e += 128) {
        int qn = e >> 6, kn = e & 63;
        int qi2 = qn >> 3, qj = qn & 7, ki = kn >> 3, kj = kn & 7;
        int rel = (qi2 - ki + 7) * 15 + (qj - kj + 7);
        float v = rpb[rel * HEADS + head];
        int gqh = wh * 8 + qi2, gqw = ww * 8 + qj;
        int gkh = wh * 8 + ki,  gkw = ww * 8 + kj;
        int rq = (gqh < 120 ? 0 : (gqh < 124 ? 1 : 2)) * 3 + (gqw < 120 ? 0 : (gqw < 124 ? 1 : 2));
        int rk = (gkh < 120 ? 0 : (gkh < 124 ? 1 : 2)) * 3 + (gkw < 120 ? 0 : (gkw < 124 ? 1 : 2));
        if (rq != rk) v -= 100.0f;
        Ps[kn * 64 + qn] = v;
    }
    __syncthreads();

    int qi = tid;
    int qn = qi & 63;
    float q[32];
    size_t qbase = ((size_t)(win * 128 + qi)) * 384 + head * 32;
#pragma unroll
    for (int d = 0; d < 32; d++) q[d] = qkv[qbase + d] * 0.17677669529663687f; // 1/sqrt(32)

    float m = -1e30f, l = 0.f, o[32];
#pragma unroll
    for (int d = 0; d < 32; d++) o[d] = 0.f;

    for (int kt = 0; kt < 128; kt++) {
        float s = Ps[(kt & 63) * 64 + qn];
#pragma unroll
        for (int d = 0; d < 32; d++) s += q[d] * Ks[kt * 32 + d];
        float mn = fmaxf(m, s);
        float corr = __expf(m - mn);
        float p = __expf(s - mn);
        l = l * corr + p;
#pragma unroll
        for (int d = 0; d < 32; d++) o[d] = o[d] * corr + p * Vs[kt * 32 + d];
        m = mn;
    }
    float inv = 1.0f / l;
    size_t obase = ((size_t)(win * 128 + qi)) * 128 + head * 32;
#pragma unroll
    for (int d = 0; d < 32; d++) attout[obase + d] = o[d] * inv;
}

// ---------------- layernorm over C=128 ----------------
__global__ void ln_kernel(const float* __restrict__ in, const float* __restrict__ g,
                          const float* __restrict__ bta, float* __restrict__ out) {
    int row = blockIdx.x;
    int c = threadIdx.x;   // 128
    float x = in[(size_t)row * 128 + c];
    float s = x;
#pragma unroll
    for (int off = 16; off; off >>= 1) s += __shfl_xor_sync(0xffffffffu, s, off);
    __shared__ float sm[4], sv[4];
    int wp = c >> 5, ln = c & 31;
    if (ln == 0) sm[wp] = s;
    __syncthreads();
    float mu = (sm[0] + sm[1] + sm[2] + sm[3]) * (1.f / 128.f);
    float d = x - mu;
    float v2 = d * d;
#pragma unroll
    for (int off = 16; off; off >>= 1) v2 += __shfl_xor_sync(0xffffffffu, v2, off);
    if (ln == 0) sv[wp] = v2;
    __syncthreads();
    float var = (sv[0] + sv[1] + sv[2] + sv[3]) * (1.f / 128.f);
    out[(size_t)row * 128 + c] = d * rsqrtf(var + 1e-5f) * g[c] + bta[c];
}

// ---------------- launch ----------------
extern "C" void kernel_launch(void* const* d_in, const int* in_sizes, int n_in,
                              void* d_out, int out_size) {
    const float* x_v    = (const float*)d_in[0];
    const float* qkv_w  = (const float*)d_in[1];
    const float* qkv_b  = (const float*)d_in[2];
    const float* proj_w = (const float*)d_in[3];
    const float* proj_b = (const float*)d_in[4];
    const float* rpb    = (const float*)d_in[5];
    const float* n1w    = (const float*)d_in[6];
    const float* n1b    = (const float*)d_in[7];
    const float* n2w    = (const float*)d_in[8];
    const float* n2b    = (const float*)d_in[9];
    const float* fc1w   = (const float*)d_in[10];
    const float* fc1b   = (const float*)d_in[11];
    const float* fc2w   = (const float*)d_in[12];
    const float* fc2b   = (const float*)d_in[13];
    float* out = (float*)d_out;

    float *xw, *qkvb, *attn, *xres, *h1;
    cudaGetSymbolAddress((void**)&xw,   g_xw);
    cudaGetSymbolAddress((void**)&qkvb, g_qkv);
    cudaGetSymbolAddress((void**)&attn, g_attn);
    cudaGetSymbolAddress((void**)&xres, g_xres);
    cudaGetSymbolAddress((void**)&h1,   g_h1);
    float* proj = xw;    // reuse: xw dead after qkv GEMM
    float* xln  = qkvb;  // reuse: qkv dead after attention
    float* pre  = attn;  // reuse: attn dead after proj GEMM

    // 1. gather (roll + window partition)
    gather_kernel<<<16384, 256>>>(x_v, xw);
    // 2. qkv = xw @ qkv_w^T + b     (M=131072, N=384, K=128)
    gemm_kernel<0><<<dim3(6, 2048), 256>>>(xw, qkv_w, qkv_b, nullptr, qkvb, 384, 128);
    // 3. fused window attention
    attn_kernel<<<dim3(1024, HEADS), 128>>>(qkvb, rpb, attn);
    // 4. proj GEMM (N=128, K=128)
    gemm_kernel<0><<<dim3(2, 2048), 256>>>(attn, proj_w, proj_b, nullptr, proj, 128, 128);
    // 5. window reverse + roll back + residual
    scatter_kernel<<<16384, 256>>>(x_v, proj, xres);
    // 6. LN2
    ln_kernel<<<131072, 128>>>(xres, n2w, n2b, xln);
    // 7. fc1 + gelu (N=512, K=128)
    gemm_kernel<1><<<dim3(8, 2048), 256>>>(xln, fc1w, fc1b, nullptr, h1, 512, 128);
    // 8. fc2 + residual (N=128, K=512)
    gemm_kernel<2><<<dim3(2, 2048), 256>>>(h1, fc2w, fc2b, xres, pre, 128, 512);
    // 9. LN1 -> output
    ln_kernel<<<131072, 128>>>(pre, n1w, n1b, out);
}

// round 2
// speedup vs baseline: 1.7546x; 1.7546x over previous
#include <cuda_runtime.h>
#include <math.h>

// ---------------- problem constants ----------------
#define M_TOT 131072          // B*nW*T*N == B*T*H*W tokens
#define CDIM  128
#define HIDDEN 512
#define HEADS 4

// ---------------- scratch (device globals, no runtime alloc) ----------------
__device__ float g_qkv [(size_t)M_TOT * 3 * CDIM];    // qkv / reused: xln overlay
__device__ float g_attn[(size_t)M_TOT * CDIM];        // attention out / reused: pre-LN1
__device__ float g_xres[(size_t)M_TOT * CDIM];        // shortcut + attn (residual stream)
__device__ float g_h1  [(size_t)M_TOT * HIDDEN];      // MLP hidden

// row permutation: window-order row -> spatial row (roll -4,-4 gather source;
// identical map is the scatter destination for window reverse + roll +4,+4)
__device__ __forceinline__ int perm_row(int r) {
    int b_ = r >> 7, tt = r & 127;
    int b = b_ >> 8, w = b_ & 255;
    int wh = w >> 4, ww = w & 15;
    int t = tt >> 6, n = tt & 63;
    int i = n >> 3, j = n & 7;
    int oh = (wh * 8 + i + 4) & 127;
    int ow = (ww * 8 + j + 4) & 127;
    return (b * 2 + t) * 16384 + oh * 128 + ow;
}

__device__ __forceinline__ unsigned f2tf(float f) {
    unsigned u;
    asm("cvt.rna.tf32.f32 %0, %1;" : "=r"(u) : "f"(f));
    return u;
}

#define MMA_TF32(d, a0, a1, a2, a3, b0, b1)                                            \
    asm volatile(                                                                      \
        "mma.sync.aligned.m16n8k8.row.col.f32.tf32.tf32.f32 "                          \
        "{%0,%1,%2,%3},{%4,%5,%6,%7},{%8,%9},{%0,%1,%2,%3};"                           \
        : "+f"(d[0]), "+f"(d[1]), "+f"(d[2]), "+f"(d[3])                               \
        : "r"(a0), "r"(a1), "r"(a2), "r"(a3), "r"(b0), "r"(b1))

// ---------------- tf32 tensor-core GEMM ----------------
// out[M,N] = A[M,K] @ Wt[N,K]^T + bias, with fused epilogues/permutations.
// EPI 0: qkv   — A rows read through perm_row (fused gather), plain write
// EPI 1: proj  — plain A, write to out[perm(r)] += res[perm(r)] (fused scatter+residual)
// EPI 2: fc1   — bias + exact gelu
// EPI 3: fc2   — bias + residual add (res, row-aligned)
// Block: 256 thr (8 warps as 4m x 2n), tile BM=128 BN=64 BK=32.
template <int EPI>
__global__ __launch_bounds__(256) void mma_gemm(
    const float* __restrict__ A, const float* __restrict__ Wt,
    const float* __restrict__ bias, const float* __restrict__ res,
    float* __restrict__ out, int Nn, int K) {
    // fragment-ordered smem, k8 stride 66 keeps STS and LDS conflict-free
    __shared__ __align__(16) unsigned As[16 * 264];   // (m16*2+half)*264 + k8*66 + (g*4+t)*2 + kh
    __shared__ __align__(16) unsigned Bs[8 * 264];    // n8*264 + k8*66 + (g*4+t)*2 + kh

    const int tid = threadIdx.x;
    const int lane = tid & 31;
    const int wid = tid >> 5;
    const int wm = wid >> 1, wn = wid & 1;
    const int g = lane >> 2, t = lane & 3;
    const int bm = blockIdx.y * 128, bn = blockIdx.x * 64;

    float acc[2][4][4];
#pragma unroll
    for (int mi = 0; mi < 2; mi++)
#pragma unroll
        for (int ni = 0; ni < 4; ni++)
#pragma unroll
            for (int c = 0; c < 4; c++) acc[mi][ni][c] = 0.f;

    for (int kt = 0; kt < K; kt += 32) {
        // load A tile 128x32
#pragma unroll
        for (int it = 0; it < 4; it++) {
            int c = tid + it * 256;           // 0..1023
            int row = c >> 3, kq = c & 7;
            int grow = bm + row;
            int src = (EPI == 0) ? perm_row(grow) : grow;
            float4 v = *reinterpret_cast<const float4*>(A + (size_t)src * K + kt + kq * 4);
            int m16 = row >> 4, half = (row >> 3) & 1, gg = row & 7;
            int k8 = kq >> 1, kh = kq & 1;
            int base = (m16 * 2 + half) * 264 + k8 * 66 + gg * 8 + kh;
            As[base + 0] = f2tf(v.x);
            As[base + 2] = f2tf(v.y);
            As[base + 4] = f2tf(v.z);
            As[base + 6] = f2tf(v.w);
        }
        // load B tile 64x32
#pragma unroll
        for (int it = 0; it < 2; it++) {
            int c = tid + it * 256;           // 0..511
            int n = c >> 3, kq = c & 7;
            float4 v = *reinterpret_cast<const float4*>(Wt + (size_t)(bn + n) * K + kt + kq * 4);
            int n8 = n >> 3, gg = n & 7;
            int k8 = kq >> 1, kh = kq & 1;
            int base = n8 * 264 + k8 * 66 + gg * 8 + kh;
            Bs[base + 0] = f2tf(v.x);
            Bs[base + 2] = f2tf(v.y);
            Bs[base + 4] = f2tf(v.z);
            Bs[base + 6] = f2tf(v.w);
        }
        __syncthreads();
#pragma unroll
        for (int k8 = 0; k8 < 4; k8++) {
            unsigned a[2][4], b[4][2];
#pragma unroll
            for (int mi = 0; mi < 2; mi++) {
                int base = ((wm * 2 + mi) * 2) * 264 + k8 * 66 + lane * 2;
                uint2 q0 = *reinterpret_cast<const uint2*>(&As[base]);
                uint2 q1 = *reinterpret_cast<const uint2*>(&As[base + 264]);
                a[mi][0] = q0.x; a[mi][2] = q0.y;
                a[mi][1] = q1.x; a[mi][3] = q1.y;
            }
#pragma unroll
            for (int ni = 0; ni < 4; ni++) {
                int base = (wn * 4 + ni) * 264 + k8 * 66 + lane * 2;
                uint2 q = *reinterpret_cast<const uint2*>(&Bs[base]);
                b[ni][0] = q.x; b[ni][1] = q.y;
            }
#pragma unroll
            for (int mi = 0; mi < 2; mi++)
#pragma unroll
                for (int ni = 0; ni < 4; ni++)
                    MMA_TF32(acc[mi][ni], a[mi][0], a[mi][1], a[mi][2], a[mi][3],
                             b[ni][0], b[ni][1]);
        }
        __syncthreads();
    }

    // epilogue
#pragma unroll
    for (int mi = 0; mi < 2; mi++) {
        int r0 = bm + wm * 32 + mi * 16 + g;
#pragma unroll
        for (int rh = 0; rh < 2; rh++) {
            int r = r0 + rh * 8;
            int dstrow = (EPI == 1) ? perm_row(r) : r;
#pragma unroll
            for (int ni = 0; ni < 4; ni++) {
                int c0 = bn + wn * 32 + ni * 8 + t * 2;
#pragma unroll
                for (int ch = 0; ch < 2; ch++) {
                    int c = c0 + ch;
                    float v = acc[mi][ni][rh * 2 + ch] + bias[c];
                    if (EPI == 1) v += res[(size_t)dstrow * Nn + c];
                    if (EPI == 2) v = 0.5f * v * (1.0f + erff(v * 0.7071067811865475f));
                    if (EPI == 3) v += res[(size_t)r * Nn + c];
                    out[(size_t)dstrow * Nn + c] = v;
                }
            }
        }
    }
}

// ---------------- fused window attention: one block per (window, head) ----------------
__global__ void attn_kernel(const float* __restrict__ qkv, const float* __restrict__ rpb,
                            float* __restrict__ attout) {
    int win  = blockIdx.x;     // 0..1023
    int head = blockIdx.y;     // 0..3
    __shared__ float Ks[128 * 32];
    __shared__ float Vs[128 * 32];
    __shared__ float Ps[64 * 64];   // rpb + shift-mask, [kn][qn]
    int tid = threadIdx.x;          // 128

    for (int e = tid; e < 128 * 32; e += 128) {
        int kt = e >> 5, d = e & 31;
        size_t base = ((size_t)(win * 128 + kt)) * 384 + head * 32 + d;
        Ks[e] = qkv[base + 128];
        Vs[e] = qkv[base + 256];
    }
    int w = win & 255;
    int wh = w >> 4, ww = w & 15;
    for (int e = tid; e < 64 * 64; e += 128) {
        int qn = e >> 6, kn = e & 63;
        int qi2 = qn >> 3, qj = qn & 7, ki = kn >> 3, kj = kn & 7;
        int rel = (qi2 - ki + 7) * 15 + (qj - kj + 7);
        float v = rpb[rel * HEADS + head];
        int gqh = wh * 8 + qi2, gqw = ww * 8 + qj;
        int gkh = wh * 8 + ki,  gkw = ww * 8 + kj;
        int rq = (gqh < 120 ? 0 : (gqh < 124 ? 1 : 2)) * 3 + (gqw < 120 ? 0 : (gqw < 124 ? 1 : 2));
        int rk = (gkh < 120 ? 0 : (gkh < 124 ? 1 : 2)) * 3 + (gkw < 120 ? 0 : (gkw < 124 ? 1 : 2));
        if (rq != rk) v -= 100.0f;
        Ps[kn * 64 + qn] = v;
    }
    __syncthreads();

    int qi = tid;
    int qn = qi & 63;
    float q[32];
    size_t qbase = ((size_t)(win * 128 + qi)) * 384 + head * 32;
#pragma unroll
    for (int d = 0; d < 32; d++) q[d] = qkv[qbase + d] * 0.17677669529663687f; // 1/sqrt(32)

    float m = -1e30f, l = 0.f, o[32];
#pragma unroll
    for (int d = 0; d < 32; d++) o[d] = 0.f;

    for (int kt = 0; kt < 128; kt++) {
        float s = Ps[(kt & 63) * 64 + qn];
#pragma unroll
        for (int d = 0; d < 32; d++) s += q[d] * Ks[kt * 32 + d];
        float mn = fmaxf(m, s);
        float corr = __expf(m - mn);
        float p = __expf(s - mn);
        l = l * corr + p;
#pragma unroll
        for (int d = 0; d < 32; d++) o[d] = o[d] * corr + p * Vs[kt * 32 + d];
        m = mn;
    }
    float inv = 1.0f / l;
    size_t obase = ((size_t)(win * 128 + qi)) * 128 + head * 32;
#pragma unroll
    for (int d = 0; d < 32; d++) attout[obase + d] = o[d] * inv;
}

// ---------------- layernorm over C=128 ----------------
__global__ void ln_kernel(const float* __restrict__ in, const float* __restrict__ g,
                          const float* __restrict__ bta, float* __restrict__ out) {
    int row = blockIdx.x;
    int c = threadIdx.x;   // 128
    float x = in[(size_t)row * 128 + c];
    float s = x;
#pragma unroll
    for (int off = 16; off; off >>= 1) s += __shfl_xor_sync(0xffffffffu, s, off);
    __shared__ float sm[4], sv[4];
    int wp = c >> 5, ln = c & 31;
    if (ln == 0) sm[wp] = s;
    __syncthreads();
    float mu = (sm[0] + sm[1] + sm[2] + sm[3]) * (1.f / 128.f);
    float d = x - mu;
    float v2 = d * d;
#pragma unroll
    for (int off = 16; off; off >>= 1) v2 += __shfl_xor_sync(0xffffffffu, v2, off);
    if (ln == 0) sv[wp] = v2;
    __syncthreads();
    float var = (sv[0] + sv[1] + sv[2] + sv[3]) * (1.f / 128.f);
    out[(size_t)row * 128 + c] = d * rsqrtf(var + 1e-5f) * g[c] + bta[c];
}

// ---------------- launch ----------------
extern "C" void kernel_launch(void* const* d_in, const int* in_sizes, int n_in,
                              void* d_out, int out_size) {
    const float* x_v    = (const float*)d_in[0];
    const float* qkv_w  = (const float*)d_in[1];
    const float* qkv_b  = (const float*)d_in[2];
    const float* proj_w = (const float*)d_in[3];
    const float* proj_b = (const float*)d_in[4];
    const float* rpb    = (const float*)d_in[5];
    const float* n1w    = (const float*)d_in[6];
    const float* n1b    = (const float*)d_in[7];
    const float* n2w    = (const float*)d_in[8];
    const float* n2b    = (const float*)d_in[9];
    const float* fc1w   = (const float*)d_in[10];
    const float* fc1b   = (const float*)d_in[11];
    const float* fc2w   = (const float*)d_in[12];
    const float* fc2b   = (const float*)d_in[13];
    float* out = (float*)d_out;

    float *qkvb, *attn, *xres, *h1;
    cudaGetSymbolAddress((void**)&qkvb, g_qkv);
    cudaGetSymbolAddress((void**)&attn, g_attn);
    cudaGetSymbolAddress((void**)&xres, g_xres);
    cudaGetSymbolAddress((void**)&h1,   g_h1);
    float* xln = qkvb;   // reuse: qkv dead after attention
    float* pre = attn;   // reuse: attn dead after proj GEMM

    // 1. qkv = gather(x_v) @ qkv_w^T + b   (fused gather; M=131072, N=384, K=128)
    mma_gemm<0><<<dim3(6, 1024), 256>>>(x_v, qkv_w, qkv_b, nullptr, qkvb, 384, 128);
    // 2. fused window attention
    attn_kernel<<<dim3(1024, HEADS), 128>>>(qkvb, rpb, attn);
    // 3. proj GEMM + fused window-reverse scatter + residual (N=128, K=128)
    mma_gemm<1><<<dim3(2, 1024), 256>>>(attn, proj_w, proj_b, x_v, xres, 128, 128);
    // 4. LN2
    ln_kernel<<<131072, 128>>>(xres, n2w, n2b, xln);
    // 5. fc1 + gelu (N=512, K=128)
    mma_gemm<2><<<dim3(8, 1024), 256>>>(xln, fc1w, fc1b, nullptr, h1, 512, 128);
    // 6. fc2 + residual (N=128, K=512)
    mma_gemm<3><<<dim3(2, 1024), 256>>>(h1, fc2w, fc2b, xres, pre, 128, 512);
    // 7. LN1 -> output
    ln_kernel<<<131072, 128>>>(pre, n1w, n1b, out);
}

// round 3
// speedup vs baseline: 2.7664x; 1.5766x over previous
#include <cuda_runtime.h>
#include <math.h>

// ---------------- problem constants ----------------
#define M_TOT 131072          // B*nW*T*N == B*T*H*W tokens
#define CDIM  128
#define HIDDEN 512
#define HEADS 4

// ---------------- scratch (device globals, no runtime alloc) ----------------
__device__ float g_qkv [(size_t)M_TOT * 3 * CDIM];    // qkv / reused: xln overlay
__device__ float g_attn[(size_t)M_TOT * CDIM];        // attention out / reused: pre-LN1
__device__ float g_xres[(size_t)M_TOT * CDIM];        // shortcut + attn (residual stream)
__device__ float g_h1  [(size_t)M_TOT * HIDDEN];      // MLP hidden

// row permutation: window-order row -> spatial row (roll -4,-4 gather source;
// identical map is the scatter destination for window reverse + roll +4,+4)
__device__ __forceinline__ int perm_row(int r) {
    int b_ = r >> 7, tt = r & 127;
    int b = b_ >> 8, w = b_ & 255;
    int wh = w >> 4, ww = w & 15;
    int t = tt >> 6, n = tt & 63;
    int i = n >> 3, j = n & 7;
    int oh = (wh * 8 + i + 4) & 127;
    int ow = (ww * 8 + j + 4) & 127;
    return (b * 2 + t) * 16384 + oh * 128 + ow;
}

__device__ __forceinline__ unsigned f2tf(float f) {
    unsigned u;
    asm("cvt.rna.tf32.f32 %0, %1;" : "=r"(u) : "f"(f));
    return u;
}

#define MMA_TF32(d, a0, a1, a2, a3, b0, b1)                                            \
    asm volatile(                                                                      \
        "mma.sync.aligned.m16n8k8.row.col.f32.tf32.tf32.f32 "                          \
        "{%0,%1,%2,%3},{%4,%5,%6,%7},{%8,%9},{%0,%1,%2,%3};"                           \
        : "+f"(d[0]), "+f"(d[1]), "+f"(d[2]), "+f"(d[3])                               \
        : "r"(a0), "r"(a1), "r"(a2), "r"(a3), "r"(b0), "r"(b1))

// ---------------- tf32 tensor-core GEMM (k-pipelined) ----------------
// out[M,N] = A[M,K] @ Wt[N,K]^T + bias, with fused epilogues/permutations.
// EPI 0: qkv   — A rows read through perm_row (fused gather), plain write
// EPI 1: proj  — plain A, write to out[perm(r)] += res[perm(r)] (fused scatter+residual)
// EPI 2: fc1   — bias + exact gelu
// EPI 3: fc2   — bias + residual add (res, row-aligned)
template <int EPI>
__global__ __launch_bounds__(256) void mma_gemm(
    const float* __restrict__ A, const float* __restrict__ Wt,
    const float* __restrict__ bias, const float* __restrict__ res,
    float* __restrict__ out, int Nn, int K) {
    __shared__ __align__(16) unsigned As[16 * 264];
    __shared__ __align__(16) unsigned Bs[8 * 264];

    const int tid = threadIdx.x;
    const int lane = tid & 31;
    const int wid = tid >> 5;
    const int wm = wid >> 1, wn = wid & 1;
    const int g = lane >> 2, t = lane & 3;
    const int bm = blockIdx.y * 128, bn = blockIdx.x * 64;

    // precompute per-thread load coordinates
    int aRow[4], aKq[4], aSrc[4], aSts[4];
#pragma unroll
    for (int it = 0; it < 4; it++) {
        int c = tid + it * 256;
        int row = c >> 3, kq = c & 7;
        aRow[it] = row; aKq[it] = kq;
        int grow = bm + row;
        aSrc[it] = (EPI == 0) ? perm_row(grow) : grow;
        int m16 = row >> 4, half = (row >> 3) & 1, gg = row & 7;
        aSts[it] = (m16 * 2 + half) * 264 + (kq >> 1) * 66 + gg * 8 + (kq & 1);
    }
    int bN[2], bKq[2], bSts[2];
#pragma unroll
    for (int it = 0; it < 2; it++) {
        int c = tid + it * 256;
        int n = c >> 3, kq = c & 7;
        bN[it] = bn + n; bKq[it] = kq;
        bSts[it] = (n >> 3) * 264 + (kq >> 1) * 66 + (n & 7) * 8 + (kq & 1);
    }

    float acc[2][4][4];
#pragma unroll
    for (int mi = 0; mi < 2; mi++)
#pragma unroll
        for (int ni = 0; ni < 4; ni++)
#pragma unroll
            for (int c = 0; c < 4; c++) acc[mi][ni][c] = 0.f;

    float4 av[4], bv[2];
#pragma unroll
    for (int it = 0; it < 4; it++)
        av[it] = *reinterpret_cast<const float4*>(A + (size_t)aSrc[it] * K + aKq[it] * 4);
#pragma unroll
    for (int it = 0; it < 2; it++)
        bv[it] = *reinterpret_cast<const float4*>(Wt + (size_t)bN[it] * K + bKq[it] * 4);

    for (int kt = 0; kt < K; kt += 32) {
#pragma unroll
        for (int it = 0; it < 4; it++) {
            As[aSts[it] + 0] = f2tf(av[it].x);
            As[aSts[it] + 2] = f2tf(av[it].y);
            As[aSts[it] + 4] = f2tf(av[it].z);
            As[aSts[it] + 6] = f2tf(av[it].w);
        }
#pragma unroll
        for (int it = 0; it < 2; it++) {
            Bs[bSts[it] + 0] = f2tf(bv[it].x);
            Bs[bSts[it] + 2] = f2tf(bv[it].y);
            Bs[bSts[it] + 4] = f2tf(bv[it].z);
            Bs[bSts[it] + 6] = f2tf(bv[it].w);
        }
        __syncthreads();
        if (kt + 32 < K) {
#pragma unroll
            for (int it = 0; it < 4; it++)
                av[it] = *reinterpret_cast<const float4*>(A + (size_t)aSrc[it] * K + kt + 32 + aKq[it] * 4);
#pragma unroll
            for (int it = 0; it < 2; it++)
                bv[it] = *reinterpret_cast<const float4*>(Wt + (size_t)bN[it] * K + kt + 32 + bKq[it] * 4);
        }
#pragma unroll
        for (int k8 = 0; k8 < 4; k8++) {
            unsigned a[2][4], b[4][2];
#pragma unroll
            for (int mi = 0; mi < 2; mi++) {
                int base = ((wm * 2 + mi) * 2) * 264 + k8 * 66 + lane * 2;
                uint2 q0 = *reinterpret_cast<const uint2*>(&As[base]);
                uint2 q1 = *reinterpret_cast<const uint2*>(&As[base + 264]);
                a[mi][0] = q0.x; a[mi][2] = q0.y;
                a[mi][1] = q1.x; a[mi][3] = q1.y;
            }
#pragma unroll
            for (int ni = 0; ni < 4; ni++) {
                int base = (wn * 4 + ni) * 264 + k8 * 66 + lane * 2;
                uint2 q = *reinterpret_cast<const uint2*>(&Bs[base]);
                b[ni][0] = q.x; b[ni][1] = q.y;
            }
#pragma unroll
            for (int mi = 0; mi < 2; mi++)
#pragma unroll
                for (int ni = 0; ni < 4; ni++)
                    MMA_TF32(acc[mi][ni], a[mi][0], a[mi][1], a[mi][2], a[mi][3],
                             b[ni][0], b[ni][1]);
        }
        __syncthreads();
    }

    // epilogue
#pragma unroll
    for (int mi = 0; mi < 2; mi++) {
        int r0 = bm + wm * 32 + mi * 16 + g;
#pragma unroll
        for (int rh = 0; rh < 2; rh++) {
            int r = r0 + rh * 8;
            int dstrow = (EPI == 1) ? perm_row(r) : r;
#pragma unroll
            for (int ni = 0; ni < 4; ni++) {
                int c0 = bn + wn * 32 + ni * 8 + t * 2;
#pragma unroll
                for (int ch = 0; ch < 2; ch++) {
                    int c = c0 + ch;
                    float v = acc[mi][ni][rh * 2 + ch] + bias[c];
                    if (EPI == 1) v += res[(size_t)dstrow * Nn + c];
                    if (EPI == 2) v = 0.5f * v * (1.0f + erff(v * 0.7071067811865475f));
                    if (EPI == 3) v += res[(size_t)r * Nn + c];
                    out[(size_t)dstrow * Nn + c] = v;
                }
            }
        }
    }
}

// ---------------- tensor-core window attention ----------------
// one block (256 thr, 8 warps) per (window, head); warp w owns S rows [16w,16w+16)
// smem layout (unsigned units):
//   QA [16*264]  A-fragment-order Q (128x32, tf32)
//   KB [16*264]  B-fragment-order K (n=128 tokens x k=32)
//   VB [4*1064]  B-fragment-order V (k=128 tokens x n=32 dims), padded chunks
//   Psf[4096]    rpb+mask in C-fragment order: [qtile(4)][ntile(8)][lane(32)][4]
#define SM_QA 0
#define SM_KB 4224
#define SM_VB 8448
#define SM_PS 12704
#define SMEM_ATTN ((12704 + 4096) * 4)

__global__ __launch_bounds__(256) void attn_kernel(const float* __restrict__ qkv,
                                                   const float* __restrict__ rpb,
                                                   float* __restrict__ attout) {
    extern __shared__ unsigned sm[];
    unsigned* QA = sm + SM_QA;
    unsigned* KB = sm + SM_KB;
    unsigned* VB = sm + SM_VB;
    float* Psf = (float*)(sm + SM_PS);

    const int win = blockIdx.x, head = blockIdx.y;
    const int tid = threadIdx.x;
    const int lane = tid & 31, w = tid >> 5;
    const int g = lane >> 2, t = lane & 3;
    const float scale = 0.17677669529663687f;  // 1/sqrt(32)

    // ---- stage Q, K, V ----
#pragma unroll
    for (int it = 0; it < 4; it++) {
        int c = tid + it * 256;          // 0..1023
        int row = c >> 3, kq = c & 7;
        size_t base = ((size_t)(win * 128 + row)) * 384 + head * 32 + kq * 4;
        float4 qv = *reinterpret_cast<const float4*>(qkv + base);
        float4 kv = *reinterpret_cast<const float4*>(qkv + base + 128);
        float4 vv = *reinterpret_cast<const float4*>(qkv + base + 256);
        int k8 = kq >> 1, kh = kq & 1;
        // Q: A-layout
        int qa = ((row >> 4) * 2 + ((row >> 3) & 1)) * 264 + k8 * 66 + (row & 7) * 8 + kh;
        QA[qa + 0] = f2tf(qv.x * scale); QA[qa + 2] = f2tf(qv.y * scale);
        QA[qa + 4] = f2tf(qv.z * scale); QA[qa + 6] = f2tf(qv.w * scale);
        // K: B-layout (n = token row)
        int kb = (row >> 3) * 264 + k8 * 66 + (row & 7) * 8 + kh;
        KB[kb + 0] = f2tf(kv.x); KB[kb + 2] = f2tf(kv.y);
        KB[kb + 4] = f2tf(kv.z); KB[kb + 6] = f2tf(kv.w);
        // V: B-layout (k = token row, n = dim d = kq*4 + i)
        int vb = (kq >> 1) * 1064 + (row >> 3) * 66 + ((kq & 1) * 4) * 8 +
                 ((row >> 2) & 1) + 2 * (row & 3);
        VB[vb + 0]  = f2tf(vv.x); VB[vb + 8]  = f2tf(vv.y);
        VB[vb + 16] = f2tf(vv.z); VB[vb + 24] = f2tf(vv.w);
    }

    // ---- rpb + shift-mask, stored in C-fragment order ----
    {
        int wwin = win & 255;
        int wh = wwin >> 4, ww = wwin & 15;
#pragma unroll
        for (int it = 0; it < 16; it++) {
            int e = tid + it * 256;      // (qn, kn) over 64x64
            int qn = e >> 6, kn = e & 63;
            int qi2 = qn >> 3, qj = qn & 7, ki = kn >> 3, kj = kn & 7;
            int rel = (qi2 - ki + 7) * 15 + (qj - kj + 7);
            float v = rpb[rel * HEADS + head];
            int gqh = wh * 8 + qi2, gqw = ww * 8 + qj;
            int gkh = wh * 8 + ki,  gkw = ww * 8 + kj;
            int rq = (gqh < 120 ? 0 : (gqh < 124 ? 1 : 2)) * 3 + (gqw < 120 ? 0 : (gqw < 124 ? 1 : 2));
            int rk = (gkh < 120 ? 0 : (gkh < 124 ? 1 : 2)) * 3 + (gkw < 120 ? 0 : (gkw < 124 ? 1 : 2));
            if (rq != rk) v -= 100.0f;
            int qtile = qn >> 4, ntile = kn >> 3;
            int ln = (qn & 7) * 4 + ((kn & 7) >> 1);
            int reg = ((qn >> 3) & 1) * 2 + (kn & 1);
            Psf[((qtile * 8 + ntile) * 32 + ln) * 4 + reg] = v;
        }
    }
    __syncthreads();

    // ---- S = Q @ K^T  (warp w: rows 16w..16w+15, all 128 cols) ----
    float acc[16][4];
#pragma unroll
    for (int nt = 0; nt < 16; nt++)
#pragma unroll
        for (int i = 0; i < 4; i++) acc[nt][i] = 0.f;

#pragma unroll
    for (int k8 = 0; k8 < 4; k8++) {
        int abase = (w * 2) * 264 + k8 * 66 + lane * 2;
        uint2 q0 = *reinterpret_cast<const uint2*>(&QA[abase]);
        uint2 q1 = *reinterpret_cast<const uint2*>(&QA[abase + 264]);
#pragma unroll
        for (int nt = 0; nt < 16; nt++) {
            uint2 b = *reinterpret_cast<const uint2*>(&KB[nt * 264 + k8 * 66 + lane * 2]);
            MMA_TF32(acc[nt], q0.x, q1.x, q0.y, q1.y, b.x, b.y);
        }
    }

    // ---- add rpb+mask, softmax over 128 cols ----
    const int qtile = w & 3;
    float m0 = -1e30f, m1 = -1e30f;
#pragma unroll
    for (int nt = 0; nt < 16; nt++) {
        float4 p = *reinterpret_cast<const float4*>(&Psf[((qtile * 8 + (nt & 7)) * 32 + lane) * 4]);
        acc[nt][0] += p.x; acc[nt][1] += p.y;
        acc[nt][2] += p.z; acc[nt][3] += p.w;
        m0 = fmaxf(m0, fmaxf(acc[nt][0], acc[nt][1]));
        m1 = fmaxf(m1, fmaxf(acc[nt][2], acc[nt][3]));
    }
    m0 = fmaxf(m0, __shfl_xor_sync(0xffffffffu, m0, 1));
    m0 = fmaxf(m0, __shfl_xor_sync(0xffffffffu, m0, 2));
    m1 = fmaxf(m1, __shfl_xor_sync(0xffffffffu, m1, 1));
    m1 = fmaxf(m1, __shfl_xor_sync(0xffffffffu, m1, 2));

    float l0 = 0.f, l1 = 0.f;
#pragma unroll
    for (int nt = 0; nt < 16; nt++) {
        acc[nt][0] = __expf(acc[nt][0] - m0);
        acc[nt][1] = __expf(acc[nt][1] - m0);
        acc[nt][2] = __expf(acc[nt][2] - m1);
        acc[nt][3] = __expf(acc[nt][3] - m1);
        l0 += acc[nt][0] + acc[nt][1];
        l1 += acc[nt][2] + acc[nt][3];
    }
    l0 += __shfl_xor_sync(0xffffffffu, l0, 1);
    l0 += __shfl_xor_sync(0xffffffffu, l0, 2);
    l1 += __shfl_xor_sync(0xffffffffu, l1, 1);
    l1 += __shfl_xor_sync(0xffffffffu, l1, 2);
    float inv0 = 1.0f / l0, inv1 = 1.0f / l1;

    // convert P to tf32 bit patterns (kept in float regs)
#pragma unroll
    for (int nt = 0; nt < 16; nt++)
#pragma unroll
        for (int i = 0; i < 4; i++)
            acc[nt][i] = __uint_as_float(f2tf(acc[nt][i]));

    // ---- O = P @ V ----
    float oacc[4][4];
#pragma unroll
    for (int n8 = 0; n8 < 4; n8++)
#pragma unroll
        for (int i = 0; i < 4; i++) oacc[n8][i] = 0.f;

    const int s0 = (lane & 28) | (t >> 1);
    const int s1 = s0 + 2;
    const bool oddt = (t & 1);
#pragma unroll
    for (int c = 0; c < 16; c++) {
        float e0 = __shfl_sync(0xffffffffu, acc[c][0], s0);
        float o0 = __shfl_sync(0xffffffffu, acc[c][1], s0);
        float e1 = __shfl_sync(0xffffffffu, acc[c][2], s0);
        float o1 = __shfl_sync(0xffffffffu, acc[c][3], s0);
        float e2 = __shfl_sync(0xffffffffu, acc[c][0], s1);
        float o2 = __shfl_sync(0xffffffffu, acc[c][1], s1);
        float e3 = __shfl_sync(0xffffffffu, acc[c][2], s1);
        float o3 = __shfl_sync(0xffffffffu, acc[c][3], s1);
        unsigned a0 = __float_as_uint(oddt ? o0 : e0);
        unsigned a1 = __float_as_uint(oddt ? o1 : e1);
        unsigned a2 = __float_as_uint(oddt ? o2 : e2);
        unsigned a3 = __float_as_uint(oddt ? o3 : e3);
#pragma unroll
        for (int n8 = 0; n8 < 4; n8++) {
            uint2 b = *reinterpret_cast<const uint2*>(&VB[n8 * 1064 + c * 66 + lane * 2]);
            MMA_TF32(oacc[n8], a0, a1, a2, a3, b.x, b.y);
        }
    }

    // ---- write out: rows win*128 + 16w + g (+8), cols head*32 + n8*8 + 2t (+1) ----
    int r0 = win * 128 + w * 16 + g;
#pragma unroll
    for (int n8 = 0; n8 < 4; n8++) {
        int col = head * 32 + n8 * 8 + t * 2;
        attout[(size_t)r0 * 128 + col]           = oacc[n8][0] * inv0;
        attout[(size_t)r0 * 128 + col + 1]       = oacc[n8][1] * inv0;
        attout[(size_t)(r0 + 8) * 128 + col]     = oacc[n8][2] * inv1;
        attout[(size_t)(r0 + 8) * 128 + col + 1] = oacc[n8][3] * inv1;
    }
}

// ---------------- layernorm over C=128: one warp per row, float4, shfl-only ----------------
__global__ __launch_bounds__(256) void ln_kernel(const float* __restrict__ in,
                                                 const float* __restrict__ gw,
                                                 const float* __restrict__ bw,
                                                 float* __restrict__ out) {
    int row = blockIdx.x * 8 + (threadIdx.x >> 5);
    int lane = threadIdx.x & 31;
    float4 v = reinterpret_cast<const float4*>(in + (size_t)row * 128)[lane];
    float s = v.x + v.y + v.z + v.w;
#pragma unroll
    for (int off = 16; off; off >>= 1) s += __shfl_xor_sync(0xffffffffu, s, off);
    float mu = s * (1.f / 128.f);
    float dx = v.x - mu, dy = v.y - mu, dz = v.z - mu, dw = v.w - mu;
    float q = dx * dx + dy * dy + dz * dz + dw * dw;
#pragma unroll
    for (int off = 16; off; off >>= 1) q += __shfl_xor_sync(0xffffffffu, q, off);
    float rs = rsqrtf(q * (1.f / 128.f) + 1e-5f);
    float4 g4 = reinterpret_cast<const float4*>(gw)[lane];
    float4 b4 = reinterpret_cast<const float4*>(bw)[lane];
    float4 o;
    o.x = dx * rs * g4.x + b4.x;
    o.y = dy * rs * g4.y + b4.y;
    o.z = dz * rs * g4.z + b4.z;
    o.w = dw * rs * g4.w + b4.w;
    reinterpret_cast<float4*>(out + (size_t)row * 128)[lane] = o;
}

// ---------------- launch ----------------
extern "C" void kernel_launch(void* const* d_in, const int* in_sizes, int n_in,
                              void* d_out, int out_size) {
    const float* x_v    = (const float*)d_in[0];
    const float* qkv_w  = (const float*)d_in[1];
    const float* qkv_b  = (const float*)d_in[2];
    const float* proj_w = (const float*)d_in[3];
    const float* proj_b = (const float*)d_in[4];
    const float* rpb    = (const float*)d_in[5];
    const float* n1w    = (const float*)d_in[6];
    const float* n1b    = (const float*)d_in[7];
    const float* n2w    = (const float*)d_in[8];
    const float* n2b    = (const float*)d_in[9];
    const float* fc1w   = (const float*)d_in[10];
    const float* fc1b   = (const float*)d_in[11];
    const float* fc2w   = (const float*)d_in[12];
    const float* fc2b   = (const float*)d_in[13];
    float* out = (float*)d_out;

    float *qkvb, *attn, *xres, *h1;
    cudaGetSymbolAddress((void**)&qkvb, g_qkv);
    cudaGetSymbolAddress((void**)&attn, g_attn);
    cudaGetSymbolAddress((void**)&xres, g_xres);
    cudaGetSymbolAddress((void**)&h1,   g_h1);
    float* xln = qkvb;   // reuse: qkv dead after attention
    float* pre = attn;   // reuse: attn dead after proj GEMM

    cudaFuncSetAttribute(attn_kernel, cudaFuncAttributeMaxDynamicSharedMemorySize, SMEM_ATTN);

    // 1. qkv = gather(x_v) @ qkv_w^T + b   (fused gather; M=131072, N=384, K=128)
    mma_gemm<0><<<dim3(6, 1024), 256>>>(x_v, qkv_w, qkv_b, nullptr, qkvb, 384, 128);
    // 2. tensor-core window attention
    attn_kernel<<<dim3(1024, HEADS), 256, SMEM_ATTN>>>(qkvb, rpb, attn);
    // 3. proj GEMM + fused window-reverse scatter + residual (N=128, K=128)
    mma_gemm<1><<<dim3(2, 1024), 256>>>(attn, proj_w, proj_b, x_v, xres, 128, 128);
    // 4. LN2
    ln_kernel<<<16384, 256>>>(xres, n2w, n2b, xln);
    // 5. fc1 + gelu (N=512, K=128)
    mma_gemm<2><<<dim3(8, 1024), 256>>>(xln, fc1w, fc1b, nullptr, h1, 512, 128);
    // 6. fc2 + residual (N=128, K=512)
    mma_gemm<3><<<dim3(2, 1024), 256>>>(h1, fc2w, fc2b, xres, pre, 128, 512);
    // 7. LN1 -> output
    ln_kernel<<<16384, 256>>>(pre, n1w, n1b, out);
}

// round 4
// speedup vs baseline: 2.8016x; 1.0127x over previous
#include <cuda_runtime.h>
#include <math.h>

// ---------------- problem constants ----------------
#define M_TOT 131072          // B*nW*T*N == B*T*H*W tokens
#define CDIM  128
#define HIDDEN 512
#define HEADS 4

// ---------------- scratch (device globals, no runtime alloc) ----------------
__device__ float g_qkv [(size_t)M_TOT * 3 * CDIM];    // qkv / reused: xln overlay
__device__ float g_attn[(size_t)M_TOT * CDIM];        // attention out
__device__ float g_xres[(size_t)M_TOT * CDIM];        // shortcut + attn (residual stream)
__device__ float g_h1  [(size_t)M_TOT * HIDDEN];      // MLP hidden

// row permutation: window-order row -> spatial row
__device__ __forceinline__ int perm_row(int r) {
    int b_ = r >> 7, tt = r & 127;
    int b = b_ >> 8, w = b_ & 255;
    int wh = w >> 4, ww = w & 15;
    int t = tt >> 6, n = tt & 63;
    int i = n >> 3, j = n & 7;
    int oh = (wh * 8 + i + 4) & 127;
    int ow = (ww * 8 + j + 4) & 127;
    return (b * 2 + t) * 16384 + oh * 128 + ow;
}

__device__ __forceinline__ unsigned f2tf(float f) {
    unsigned u;
    asm("cvt.rna.tf32.f32 %0, %1;" : "=r"(u) : "f"(f));
    return u;
}

#define MMA_TF32(d, a0, a1, a2, a3, b0, b1)                                            \
    asm volatile(                                                                      \
        "mma.sync.aligned.m16n8k8.row.col.f32.tf32.tf32.f32 "                          \
        "{%0,%1,%2,%3},{%4,%5,%6,%7},{%8,%9},{%0,%1,%2,%3};"                           \
        : "+f"(d[0]), "+f"(d[1]), "+f"(d[2]), "+f"(d[3])                               \
        : "r"(a0), "r"(a1), "r"(a2), "r"(a3), "r"(b0), "r"(b1))

#define GEMM_SMEM (12672 * 4)   // 50688 B: double-buffered A + B tiles

// ---------------- tf32 GEMM, BM=128 BN=64, double-buffered ----------------
// EPI 0: qkv — A rows read through perm_row (fused gather), bias write
// EPI 2: fc1 — bias + exact gelu
template <int EPI>
__global__ __launch_bounds__(256) void mma_gemm(
    const float* __restrict__ A, const float* __restrict__ Wt,
    const float* __restrict__ bias, float* __restrict__ out, int Nn, int K) {
    extern __shared__ unsigned sm[];
    unsigned* As = sm;            // 2 bufs x 4224
    unsigned* Bs = sm + 8448;     // 2 bufs x 2112

    const int tid = threadIdx.x;
    const int lane = tid & 31;
    const int wid = tid >> 5;
    const int wm = wid >> 1, wn = wid & 1;
    const int g = lane >> 2, t = lane & 3;
    const int bm = blockIdx.y * 128, bn = blockIdx.x * 64;

    int aKq[4], aSrc[4], aSts[4];
#pragma unroll
    for (int it = 0; it < 4; it++) {
        int c = tid + it * 256;
        int row = c >> 3, kq = c & 7;
        aKq[it] = kq;
        int grow = bm + row;
        aSrc[it] = (EPI == 0) ? perm_row(grow) : grow;
        aSts[it] = ((row >> 4) * 2 + ((row >> 3) & 1)) * 264 + (kq >> 1) * 66 + (row & 7) * 8 + (kq & 1);
    }
    int bN[2], bKq[2], bSts[2];
#pragma unroll
    for (int it = 0; it < 2; it++) {
        int c = tid + it * 256;
        int n = c >> 3, kq = c & 7;
        bN[it] = bn + n; bKq[it] = kq;
        bSts[it] = (n >> 3) * 264 + (kq >> 1) * 66 + (n & 7) * 8 + (kq & 1);
    }

    float acc[2][4][4];
#pragma unroll
    for (int mi = 0; mi < 2; mi++)
#pragma unroll
        for (int ni = 0; ni < 4; ni++)
#pragma unroll
            for (int c = 0; c < 4; c++) acc[mi][ni][c] = 0.f;

    float4 av[4], bv[2];
#pragma unroll
    for (int it = 0; it < 4; it++)
        av[it] = *reinterpret_cast<const float4*>(A + (size_t)aSrc[it] * K + aKq[it] * 4);
#pragma unroll
    for (int it = 0; it < 2; it++)
        bv[it] = *reinterpret_cast<const float4*>(Wt + (size_t)bN[it] * K + bKq[it] * 4);

    int p = 0;
    for (int kt = 0; kt < K; kt += 32) {
        unsigned* Ap = As + p * 4224;
        unsigned* Bp = Bs + p * 2112;
#pragma unroll
        for (int it = 0; it < 4; it++) {
            Ap[aSts[it] + 0] = f2tf(av[it].x);
            Ap[aSts[it] + 2] = f2tf(av[it].y);
            Ap[aSts[it] + 4] = f2tf(av[it].z);
            Ap[aSts[it] + 6] = f2tf(av[it].w);
        }
#pragma unroll
        for (int it = 0; it < 2; it++) {
            Bp[bSts[it] + 0] = f2tf(bv[it].x);
            Bp[bSts[it] + 2] = f2tf(bv[it].y);
            Bp[bSts[it] + 4] = f2tf(bv[it].z);
            Bp[bSts[it] + 6] = f2tf(bv[it].w);
        }
        __syncthreads();
        if (kt + 32 < K) {
#pragma unroll
            for (int it = 0; it < 4; it++)
                av[it] = *reinterpret_cast<const float4*>(A + (size_t)aSrc[it] * K + kt + 32 + aKq[it] * 4);
#pragma unroll
            for (int it = 0; it < 2; it++)
                bv[it] = *reinterpret_cast<const float4*>(Wt + (size_t)bN[it] * K + kt + 32 + bKq[it] * 4);
        }
#pragma unroll
        for (int k8 = 0; k8 < 4; k8++) {
            unsigned a[2][4], b[4][2];
#pragma unroll
            for (int mi = 0; mi < 2; mi++) {
                int base = ((wm * 2 + mi) * 2) * 264 + k8 * 66 + lane * 2;
                uint2 q0 = *reinterpret_cast<const uint2*>(&Ap[base]);
                uint2 q1 = *reinterpret_cast<const uint2*>(&Ap[base + 264]);
                a[mi][0] = q0.x; a[mi][2] = q0.y;
                a[mi][1] = q1.x; a[mi][3] = q1.y;
            }
#pragma unroll
            for (int ni = 0; ni < 4; ni++) {
                uint2 q = *reinterpret_cast<const uint2*>(&Bp[(wn * 4 + ni) * 264 + k8 * 66 + lane * 2]);
                b[ni][0] = q.x; b[ni][1] = q.y;
            }
#pragma unroll
            for (int mi = 0; mi < 2; mi++)
#pragma unroll
                for (int ni = 0; ni < 4; ni++)
                    MMA_TF32(acc[mi][ni], a[mi][0], a[mi][1], a[mi][2], a[mi][3],
                             b[ni][0], b[ni][1]);
        }
        p ^= 1;
    }

#pragma unroll
    for (int mi = 0; mi < 2; mi++) {
        int r0 = bm + wm * 32 + mi * 16 + g;
#pragma unroll
        for (int rh = 0; rh < 2; rh++) {
            int r = r0 + rh * 8;
#pragma unroll
            for (int ni = 0; ni < 4; ni++) {
                int c0 = bn + wn * 32 + ni * 8 + t * 2;
#pragma unroll
                for (int ch = 0; ch < 2; ch++) {
                    int c = c0 + ch;
                    float v = acc[mi][ni][rh * 2 + ch] + bias[c];
                    if (EPI == 2) v = 0.5f * v * (1.0f + erff(v * 0.7071067811865475f));
                    out[(size_t)r * Nn + c] = v;
                }
            }
        }
    }
}

// ---------------- tf32 GEMM + fused residual + LayerNorm, BM=64 BN=128 ----------------
// EPI 1: proj — res/aux/dst rows at perm(r): aux=xres gets v, dst=xln gets LN(v)
// EPI 3: fc2  — res rows aligned, dst=final out gets LN(v), aux unused
template <int EPI>
__global__ __launch_bounds__(256) void mma_gemm_ln(
    const float* __restrict__ A, const float* __restrict__ Wt,
    const float* __restrict__ bias, const float* __restrict__ res,
    float* __restrict__ aux, float* __restrict__ dst,
    const float* __restrict__ gw, const float* __restrict__ bw, int K) {
    extern __shared__ unsigned sm[];
    unsigned* As = sm;            // 2 bufs x 2112
    unsigned* Bs = sm + 4224;     // 2 bufs x 4224
    __shared__ float smS[64][4], smQ[64][4];

    const int tid = threadIdx.x;
    const int lane = tid & 31;
    const int wid = tid >> 5;
    const int wm = wid >> 2, wn = wid & 3;     // 2m x 4n
    const int g = lane >> 2, t = lane & 3;
    const int bm = blockIdx.y * 64;

    int aKq[2], aSrc[2], aSts[2];
#pragma unroll
    for (int it = 0; it < 2; it++) {
        int c = tid + it * 256;
        int row = c >> 3, kq = c & 7;
        aKq[it] = kq; aSrc[it] = bm + row;
        aSts[it] = ((row >> 4) * 2 + ((row >> 3) & 1)) * 264 + (kq >> 1) * 66 + (row & 7) * 8 + (kq & 1);
    }
    int bN[4], bKq[4], bSts[4];
#pragma unroll
    for (int it = 0; it < 4; it++) {
        int c = tid + it * 256;
        int n = c >> 3, kq = c & 7;
        bN[it] = n; bKq[it] = kq;
        bSts[it] = (n >> 3) * 264 + (kq >> 1) * 66 + (n & 7) * 8 + (kq & 1);
    }

    float acc[2][4][4];
#pragma unroll
    for (int mi = 0; mi < 2; mi++)
#pragma unroll
        for (int ni = 0; ni < 4; ni++)
#pragma unroll
            for (int c = 0; c < 4; c++) acc[mi][ni][c] = 0.f;

    float4 av[2], bv[4];
#pragma unroll
    for (int it = 0; it < 2; it++)
        av[it] = *reinterpret_cast<const float4*>(A + (size_t)aSrc[it] * K + aKq[it] * 4);
#pragma unroll
    for (int it = 0; it < 4; it++)
        bv[it] = *reinterpret_cast<const float4*>(Wt + (size_t)bN[it] * K + bKq[it] * 4);

    int p = 0;
    for (int kt = 0; kt < K; kt += 32) {
        unsigned* Ap = As + p * 2112;
        unsigned* Bp = Bs + p * 4224;
#pragma unroll
        for (int it = 0; it < 2; it++) {
            Ap[aSts[it] + 0] = f2tf(av[it].x);
            Ap[aSts[it] + 2] = f2tf(av[it].y);
            Ap[aSts[it] + 4] = f2tf(av[it].z);
            Ap[aSts[it] + 6] = f2tf(av[it].w);
        }
#pragma unroll
        for (int it = 0; it < 4; it++) {
            Bp[bSts[it] + 0] = f2tf(bv[it].x);
            Bp[bSts[it] + 2] = f2tf(bv[it].y);
            Bp[bSts[it] + 4] = f2tf(bv[it].z);
            Bp[bSts[it] + 6] = f2tf(bv[it].w);
        }
        __syncthreads();
        if (kt + 32 < K) {
#pragma unroll
            for (int it = 0; it < 2; it++)
                av[it] = *reinterpret_cast<const float4*>(A + (size_t)aSrc[it] * K + kt + 32 + aKq[it] * 4);
#pragma unroll
            for (int it = 0; it < 4; it++)
                bv[it] = *reinterpret_cast<const float4*>(Wt + (size_t)bN[it] * K + kt + 32 + bKq[it] * 4);
        }
#pragma unroll
        for (int k8 = 0; k8 < 4; k8++) {
            unsigned a[2][4], b[4][2];
#pragma unroll
            for (int mi = 0; mi < 2; mi++) {
                int base = ((wm * 2 + mi) * 2) * 264 + k8 * 66 + lane * 2;
                uint2 q0 = *reinterpret_cast<const uint2*>(&Ap[base]);
                uint2 q1 = *reinterpret_cast<const uint2*>(&Ap[base + 264]);
                a[mi][0] = q0.x; a[mi][2] = q0.y;
                a[mi][1] = q1.x; a[mi][3] = q1.y;
            }
#pragma unroll
            for (int ni = 0; ni < 4; ni++) {
                uint2 q = *reinterpret_cast<const uint2*>(&Bp[(wn * 4 + ni) * 264 + k8 * 66 + lane * 2]);
                b[ni][0] = q.x; b[ni][1] = q.y;
            }
#pragma unroll
            for (int mi = 0; mi < 2; mi++)
#pragma unroll
                for (int ni = 0; ni < 4; ni++)
                    MMA_TF32(acc[mi][ni], a[mi][0], a[mi][1], a[mi][2], a[mi][3],
                             b[ni][0], b[ni][1]);
        }
        p ^= 1;
    }

    // ---- epilogue: bias + residual, then row LayerNorm over 128 cols ----
#pragma unroll
    for (int mi = 0; mi < 2; mi++) {
#pragma unroll
        for (int rh = 0; rh < 2; rh++) {
            int lrow = (wm * 2 + mi) * 16 + g + rh * 8;
            int r = bm + lrow;
            int xrow = (EPI == 1) ? perm_row(r) : r;   // residual/dest row
            float v[8];
            float s = 0.f, q = 0.f;
#pragma unroll
            for (int ni = 0; ni < 4; ni++) {
                int c = wn * 32 + ni * 8 + t * 2;
#pragma unroll
                for (int ch = 0; ch < 2; ch++) {
                    float x = acc[mi][ni][rh * 2 + ch] + bias[c + ch] +
                              res[(size_t)xrow * 128 + c + ch];
                    if (EPI == 1) aux[(size_t)xrow * 128 + c + ch] = x;
                    v[ni * 2 + ch] = x;
                    s += x; q += x * x;
                }
            }
            s += __shfl_xor_sync(0xffffffffu, s, 1);
            s += __shfl_xor_sync(0xffffffffu, s, 2);
            q += __shfl_xor_sync(0xffffffffu, q, 1);
            q += __shfl_xor_sync(0xffffffffu, q, 2);
            if (t == 0) { smS[lrow][wn] = s; smQ[lrow][wn] = q; }
            __syncthreads();
            float S = smS[lrow][0] + smS[lrow][1] + smS[lrow][2] + smS[lrow][3];
            float Q = smQ[lrow][0] + smQ[lrow][1] + smQ[lrow][2] + smQ[lrow][3];
            float mu = S * (1.f / 128.f);
            float var = Q * (1.f / 128.f) - mu * mu;
            float rs = rsqrtf(var + 1e-5f);
#pragma unroll
            for (int ni = 0; ni < 4; ni++) {
                int c = wn * 32 + ni * 8 + t * 2;
#pragma unroll
                for (int ch = 0; ch < 2; ch++) {
                    dst[(size_t)xrow * 128 + c + ch] =
                        (v[ni * 2 + ch] - mu) * rs * gw[c + ch] + bw[c + ch];
                }
            }
        }
    }
}

// ---------------- tensor-core window attention (unchanged from round 3) ----------------
#define SM_QA 0
#define SM_KB 4224
#define SM_VB 8448
#define SM_PS 12704
#define SMEM_ATTN ((12704 + 4096) * 4)

__global__ __launch_bounds__(256) void attn_kernel(const float* __restrict__ qkv,
                                                   const float* __restrict__ rpb,
                                                   float* __restrict__ attout) {
    extern __shared__ unsigned sm[];
    unsigned* QA = sm + SM_QA;
    unsigned* KB = sm + SM_KB;
    unsigned* VB = sm + SM_VB;
    float* Psf = (float*)(sm + SM_PS);

    const int win = blockIdx.x, head = blockIdx.y;
    const int tid = threadIdx.x;
    const int lane = tid & 31, w = tid >> 5;
    const int g = lane >> 2, t = lane & 3;
    const float scale = 0.17677669529663687f;

#pragma unroll
    for (int it = 0; it < 4; it++) {
        int c = tid + it * 256;
        int row = c >> 3, kq = c & 7;
        size_t base = ((size_t)(win * 128 + row)) * 384 + head * 32 + kq * 4;
        float4 qv = *reinterpret_cast<const float4*>(qkv + base);
        float4 kv = *reinterpret_cast<const float4*>(qkv + base + 128);
        float4 vv = *reinterpret_cast<const float4*>(qkv + base + 256);
        int k8 = kq >> 1, kh = kq & 1;
        int qa = ((row >> 4) * 2 + ((row >> 3) & 1)) * 264 + k8 * 66 + (row & 7) * 8 + kh;
        QA[qa + 0] = f2tf(qv.x * scale); QA[qa + 2] = f2tf(qv.y * scale);
        QA[qa + 4] = f2tf(qv.z * scale); QA[qa + 6] = f2tf(qv.w * scale);
        int kb = (row >> 3) * 264 + k8 * 66 + (row & 7) * 8 + kh;
        KB[kb + 0] = f2tf(kv.x); KB[kb + 2] = f2tf(kv.y);
        KB[kb + 4] = f2tf(kv.z); KB[kb + 6] = f2tf(kv.w);
        int vb = (kq >> 1) * 1064 + (row >> 3) * 66 + ((kq & 1) * 4) * 8 +
                 ((row >> 2) & 1) + 2 * (row & 3);
        VB[vb + 0]  = f2tf(vv.x); VB[vb + 8]  = f2tf(vv.y);
        VB[vb + 16] = f2tf(vv.z); VB[vb + 24] = f2tf(vv.w);
    }

    {
        int wwin = win & 255;
        int wh = wwin >> 4, ww = wwin & 15;
#pragma unroll
        for (int it = 0; it < 16; it++) {
            int e = tid + it * 256;
            int qn = e >> 6, kn = e & 63;
            int qi2 = qn >> 3, qj = qn & 7, ki = kn >> 3, kj = kn & 7;
            int rel = (qi2 - ki + 7) * 15 + (qj - kj + 7);
            float v = rpb[rel * HEADS + head];
            int gqh = wh * 8 + qi2, gqw = ww * 8 + qj;
            int gkh = wh * 8 + ki,  gkw = ww * 8 + kj;
            int rq = (gqh < 120 ? 0 : (gqh < 124 ? 1 : 2)) * 3 + (gqw < 120 ? 0 : (gqw < 124 ? 1 : 2));
            int rk = (gkh < 120 ? 0 : (gkh < 124 ? 1 : 2)) * 3 + (gkw < 120 ? 0 : (gkw < 124 ? 1 : 2));
            if (rq != rk) v -= 100.0f;
            int qtile = qn >> 4, ntile = kn >> 3;
            int ln = (qn & 7) * 4 + ((kn & 7) >> 1);
            int reg = ((qn >> 3) & 1) * 2 + (kn & 1);
            Psf[((qtile * 8 + ntile) * 32 + ln) * 4 + reg] = v;
        }
    }
    __syncthreads();

    float acc[16][4];
#pragma unroll
    for (int nt = 0; nt < 16; nt++)
#pragma unroll
        for (int i = 0; i < 4; i++) acc[nt][i] = 0.f;

#pragma unroll
    for (int k8 = 0; k8 < 4; k8++) {
        int abase = (w * 2) * 264 + k8 * 66 + lane * 2;
        uint2 q0 = *reinterpret_cast<const uint2*>(&QA[abase]);
        uint2 q1 = *reinterpret_cast<const uint2*>(&QA[abase + 264]);
#pragma unroll
        for (int nt = 0; nt < 16; nt++) {
            uint2 b = *reinterpret_cast<const uint2*>(&KB[nt * 264 + k8 * 66 + lane * 2]);
            MMA_TF32(acc[nt], q0.x, q1.x, q0.y, q1.y, b.x, b.y);
        }
    }

    const int qtile = w & 3;
    float m0 = -1e30f, m1 = -1e30f;
#pragma unroll
    for (int nt = 0; nt < 16; nt++) {
        float4 p = *reinterpret_cast<const float4*>(&Psf[((qtile * 8 + (nt & 7)) * 32 + lane) * 4]);
        acc[nt][0] += p.x; acc[nt][1] += p.y;
        acc[nt][2] += p.z; acc[nt][3] += p.w;
        m0 = fmaxf(m0, fmaxf(acc[nt][0], acc[nt][1]));
        m1 = fmaxf(m1, fmaxf(acc[nt][2], acc[nt][3]));
    }
    m0 = fmaxf(m0, __shfl_xor_sync(0xffffffffu, m0, 1));
    m0 = fmaxf(m0, __shfl_xor_sync(0xffffffffu, m0, 2));
    m1 = fmaxf(m1, __shfl_xor_sync(0xffffffffu, m1, 1));
    m1 = fmaxf(m1, __shfl_xor_sync(0xffffffffu, m1, 2));

    float l0 = 0.f, l1 = 0.f;
#pragma unroll
    for (int nt = 0; nt < 16; nt++) {
        acc[nt][0] = __expf(acc[nt][0] - m0);
        acc[nt][1] = __expf(acc[nt][1] - m0);
        acc[nt][2] = __expf(acc[nt][2] - m1);
        acc[nt][3] = __expf(acc[nt][3] - m1);
        l0 += acc[nt][0] + acc[nt][1];
        l1 += acc[nt][2] + acc[nt][3];
    }
    l0 += __shfl_xor_sync(0xffffffffu, l0, 1);
    l0 += __shfl_xor_sync(0xffffffffu, l0, 2);
    l1 += __shfl_xor_sync(0xffffffffu, l1, 1);
    l1 += __shfl_xor_sync(0xffffffffu, l1, 2);
    float inv0 = 1.0f / l0, inv1 = 1.0f / l1;

#pragma unroll
    for (int nt = 0; nt < 16; nt++)
#pragma unroll
        for (int i = 0; i < 4; i++)
            acc[nt][i] = __uint_as_float(f2tf(acc[nt][i]));

    float oacc[4][4];
#pragma unroll
    for (int n8 = 0; n8 < 4; n8++)
#pragma unroll
        for (int i = 0; i < 4; i++) oacc[n8][i] = 0.f;

    const int s0 = (lane & 28) | (t >> 1);
    const int s1 = s0 + 2;
    const bool oddt = (t & 1);
#pragma unroll
    for (int c = 0; c < 16; c++) {
        float e0 = __shfl_sync(0xffffffffu, acc[c][0], s0);
        float o0 = __shfl_sync(0xffffffffu, acc[c][1], s0);
        float e1 = __shfl_sync(0xffffffffu, acc[c][2], s0);
        float o1 = __shfl_sync(0xffffffffu, acc[c][3], s0);
        float e2 = __shfl_sync(0xffffffffu, acc[c][0], s1);
        float o2 = __shfl_sync(0xffffffffu, acc[c][1], s1);
        float e3 = __shfl_sync(0xffffffffu, acc[c][2], s1);
        float o3 = __shfl_sync(0xffffffffu, acc[c][3], s1);
        unsigned a0 = __float_as_uint(oddt ? o0 : e0);
        unsigned a1 = __float_as_uint(oddt ? o1 : e1);
        unsigned a2 = __float_as_uint(oddt ? o2 : e2);
        unsigned a3 = __float_as_uint(oddt ? o3 : e3);
#pragma unroll
        for (int n8 = 0; n8 < 4; n8++) {
            uint2 b = *reinterpret_cast<const uint2*>(&VB[n8 * 1064 + c * 66 + lane * 2]);
            MMA_TF32(oacc[n8], a0, a1, a2, a3, b.x, b.y);
        }
    }

    int r0 = win * 128 + w * 16 + g;
#pragma unroll
    for (int n8 = 0; n8 < 4; n8++) {
        int col = head * 32 + n8 * 8 + t * 2;
        attout[(size_t)r0 * 128 + col]           = oacc[n8][0] * inv0;
        attout[(size_t)r0 * 128 + col + 1]       = oacc[n8][1] * inv0;
        attout[(size_t)(r0 + 8) * 128 + col]     = oacc[n8][2] * inv1;
        attout[(size_t)(r0 + 8) * 128 + col + 1] = oacc[n8][3] * inv1;
    }
}

// ---------------- launch ----------------
extern "C" void kernel_launch(void* const* d_in, const int* in_sizes, int n_in,
                              void* d_out, int out_size) {
    const float* x_v    = (const float*)d_in[0];
    const float* qkv_w  = (const float*)d_in[1];
    const float* qkv_b  = (const float*)d_in[2];
    const float* proj_w = (const float*)d_in[3];
    const float* proj_b = (const float*)d_in[4];
    const float* rpb    = (const float*)d_in[5];
    const float* n1w    = (const float*)d_in[6];
    const float* n1b    = (const float*)d_in[7];
    const float* n2w    = (const float*)d_in[8];
    const float* n2b    = (const float*)d_in[9];
    const float* fc1w   = (const float*)d_in[10];
    const float* fc1b   = (const float*)d_in[11];
    const float* fc2w   = (const float*)d_in[12];
    const float* fc2b   = (const float*)d_in[13];
    float* out = (float*)d_out;

    float *qkvb, *attn, *xres, *h1;
    cudaGetSymbolAddress((void**)&qkvb, g_qkv);
    cudaGetSymbolAddress((void**)&attn, g_attn);
    cudaGetSymbolAddress((void**)&xres, g_xres);
    cudaGetSymbolAddress((void**)&h1,   g_h1);
    float* xln = qkvb;   // reuse: qkv dead after attention

    cudaFuncSetAttribute(attn_kernel, cudaFuncAttributeMaxDynamicSharedMemorySize, SMEM_ATTN);
    cudaFuncSetAttribute(mma_gemm<0>, cudaFuncAttributeMaxDynamicSharedMemorySize, GEMM_SMEM);
    cudaFuncSetAttribute(mma_gemm<2>, cudaFuncAttributeMaxDynamicSharedMemorySize, GEMM_SMEM);
    cudaFuncSetAttribute(mma_gemm_ln<1>, cudaFuncAttributeMaxDynamicSharedMemorySize, GEMM_SMEM);
    cudaFuncSetAttribute(mma_gemm_ln<3>, cudaFuncAttributeMaxDynamicSharedMemorySize, GEMM_SMEM);

    // 1. qkv = gather(x_v) @ qkv_w^T + b
    mma_gemm<0><<<dim3(6, 1024), 256, GEMM_SMEM>>>(x_v, qkv_w, qkv_b, qkvb, 384, 128);
    // 2. tensor-core window attention
    attn_kernel<<<dim3(1024, HEADS), 256, SMEM_ATTN>>>(qkvb, rpb, attn);
    // 3. proj GEMM + scatter + residual + LN2 (writes xres and xln)
    mma_gemm_ln<1><<<dim3(1, 2048), 256, GEMM_SMEM>>>(attn, proj_w, proj_b, x_v,
                                                      xres, xln, n2w, n2b, 128);
    // 4. fc1 + gelu
    mma_gemm<2><<<dim3(8, 1024), 256, GEMM_SMEM>>>(xln, fc1w, fc1b, h1, 512, 128);
    // 5. fc2 + residual + LN1 -> final output
    mma_gemm_ln<3><<<dim3(1, 2048), 256, GEMM_SMEM>>>(h1, fc2w, fc2b, xres,
                                                      nullptr, out, n1w, n1b, 512);
}